// round 16
// baseline (speedup 1.0000x reference)
#include <cuda_runtime.h>
#include <cuda_fp16.h>
#include <math.h>
#include <stdint.h>

#define BATCH   2
#define SEQ     2048
#define DMODEL  2048
#define NHEADS  16
#define DK      128
#define ROWS    (BATCH * SEQ)
#define WN      (DMODEL * DMODEL)

// ---------------- scratch ----------------------------------------------------
__device__ __half g_x16[ROWS * DMODEL];
__device__ __half g_w16[3][WN];
__device__ __half g_wo16[WN];
__device__ __half g_q16[ROWS * DMODEL];
__device__ __half g_k16[ROWS * DMODEL];
__device__ __half g_vt16[ROWS * DMODEL];   // [bh][d][s]
__device__ __half g_a16[ROWS * DMODEL];

// ---------------- helpers ----------------------------------------------------
__device__ __forceinline__ uint32_t smem_u32(const void* p) {
    return (uint32_t)__cvta_generic_to_shared(p);
}
__device__ __forceinline__ void ldmx4(uint32_t& r0, uint32_t& r1, uint32_t& r2,
                                      uint32_t& r3, uint32_t a) {
    asm volatile("ldmatrix.sync.aligned.m8n8.x4.shared.b16 {%0,%1,%2,%3},[%4];"
                 : "=r"(r0), "=r"(r1), "=r"(r2), "=r"(r3) : "r"(a));
}
__device__ __forceinline__ void mma_f16(float* c, uint32_t a0, uint32_t a1,
                                        uint32_t a2, uint32_t a3,
                                        uint32_t b0, uint32_t b1) {
    asm volatile(
        "mma.sync.aligned.m16n8k16.row.col.f32.f16.f16.f32 "
        "{%0,%1,%2,%3},{%4,%5,%6,%7},{%8,%9},{%0,%1,%2,%3};"
        : "+f"(c[0]), "+f"(c[1]), "+f"(c[2]), "+f"(c[3])
        : "r"(a0), "r"(a1), "r"(a2), "r"(a3), "r"(b0), "r"(b1));
}
__device__ __forceinline__ void cpasync16(uint32_t dst, const void* src) {
    asm volatile("cp.async.cg.shared.global [%0],[%1],16;" :: "r"(dst), "l"(src));
}
#define CP_COMMIT asm volatile("cp.async.commit_group;")
template<int N> __device__ __forceinline__ void cp_wait() {
    asm volatile("cp.async.wait_group %0;" :: "n"(N));
}
__device__ __forceinline__ uint32_t packh2(float x, float y) {
    __half2 h = __floats2half2_rn(x, y);
    return *(uint32_t*)&h;
}

// ---------------- merged converts --------------------------------------------
__global__ __launch_bounds__(256)
void convert_all(const float* __restrict__ w0, const float* __restrict__ w1,
                 const float* __restrict__ w2, const float* __restrict__ w3,
                 const float* __restrict__ x,
                 __half* __restrict__ wqkv, __half* __restrict__ wo16,
                 __half* __restrict__ x16)
{
    int z = blockIdx.y;
    const float* src;
    __half* dst;
    if (z < 4) {
        src = (z == 0) ? w0 : (z == 1) ? w1 : (z == 2) ? w2 : w3;
        dst = (z < 3) ? (wqkv + (size_t)z * WN) : wo16;
    } else {
        src = x + (size_t)(z - 4) * WN;
        dst = x16 + (size_t)(z - 4) * WN;
    }
    int i = (blockIdx.x * blockDim.x + threadIdx.x) * 4;
    float4 v = *(const float4*)(src + i);
    *(uint32_t*)&dst[i]     = packh2(v.x, v.y);
    *(uint32_t*)&dst[i + 2] = packh2(v.z, v.w);
}

// ---------------- fp16 GEMM: 4 warps, 64x64/warp, BK=64, 2-stage -------------
#define NKIT   (DMODEL / 64)
#define PLE64  (128 * 72)
#define STGE64 (2 * PLE64)
#define GSMEM2 (2 * STGE64 * 2)   // 73728 B

// GEMM mainloop as a macro-free shared pattern (duplicated in both kernels).
// Warp grid 2x2: wm = wid&1 (64 rows), wn = wid>>1 (64 cols).

// z = 0: Q (RoPE + 1/sqrt(dk)) | 1: K (RoPE) | 2: V (transposed per-head out)
__global__ __launch_bounds__(128, 2)
void gemm_proj(const __half* __restrict__ A, const __half* __restrict__ W,
               const float* __restrict__ b0, const float* __restrict__ b1,
               const float* __restrict__ b2,
               __half* __restrict__ Q16, __half* __restrict__ K16,
               __half* __restrict__ VT16)
{
    extern __shared__ __half smh[];
    const int tid = threadIdx.x, lane = tid & 31, wid = tid >> 5;
    const int wm = wid & 1, wn = wid >> 1;
    const int m0 = blockIdx.y * 128, n0 = blockIdx.x * 128;
    const int bz = blockIdx.z;
    const uint32_t sb = smem_u32(smh);
    const __half* B = W + (size_t)bz * WN;
    const float* bias = (bz == 0) ? b0 : (bz == 1) ? b1 : b2;

    auto issue = [&](int kt, int stg) {
        int kofs = kt * 64;
#pragma unroll
        for (int i = 0; i < 16; i++) {
            int idx = tid + i * 128;
            int plane = idx >> 10, rem = idx & 1023;
            int row = rem >> 3, ch = (rem & 7) * 8;
            const __half* src = plane ? (B + (size_t)(n0 + row) * DMODEL + kofs + ch)
                                      : (A + (size_t)(m0 + row) * DMODEL + kofs + ch);
            cpasync16(sb + (stg * STGE64 + plane * PLE64 + row * 72 + ch) * 2, src);
        }
    };

    float acc[4][8][4];
#pragma unroll
    for (int a = 0; a < 4; a++)
#pragma unroll
        for (int b = 0; b < 8; b++)
#pragma unroll
            for (int c = 0; c < 4; c++) acc[a][b][c] = 0.f;

    issue(0, 0); CP_COMMIT;

    for (int kt = 0; kt < NKIT; kt++) {
        cp_wait<0>();
        __syncthreads();
        if (kt + 1 < NKIT) { issue(kt + 1, (kt + 1) & 1); CP_COMMIT; }
        uint32_t s0 = sb + ((kt & 1) * STGE64) * 2;

#pragma unroll
        for (int ks = 0; ks < 64; ks += 16) {
            uint32_t av[4][4], bv[4][4];
#pragma unroll
            for (int mt = 0; mt < 4; mt++) {
                int ar = wm * 64 + mt * 16 + (lane & 15);
                int ac = ks + ((lane >> 4) << 3);
                uint32_t off = (uint32_t)(ar * 72 + ac) * 2;
                ldmx4(av[mt][0], av[mt][1], av[mt][2], av[mt][3], s0 + off);
            }
#pragma unroll
            for (int np = 0; np < 4; np++) {
                int br = wn * 64 + np * 16 + ((lane >> 4) << 3) + (lane & 7);
                int bc = ks + (((lane >> 3) & 1) << 3);
                uint32_t off = (uint32_t)(br * 72 + bc) * 2;
                ldmx4(bv[np][0], bv[np][1], bv[np][2], bv[np][3], s0 + PLE64 * 2 + off);
            }
#pragma unroll
            for (int np = 0; np < 4; np++)
#pragma unroll
                for (int mt = 0; mt < 4; mt++) {
                    mma_f16(acc[mt][2 * np],     av[mt][0], av[mt][1], av[mt][2], av[mt][3], bv[np][0], bv[np][1]);
                    mma_f16(acc[mt][2 * np + 1], av[mt][0], av[mt][1], av[mt][2], av[mt][3], bv[np][2], bv[np][3]);
                }
        }
        __syncthreads();
    }

    if (bz == 2) {
        // V: stage transposed tile, write [bh][d][s] coalesced.
#pragma unroll
        for (int mt = 0; mt < 4; mt++) {
            int rl = wm * 64 + mt * 16 + (lane >> 2);
#pragma unroll
            for (int nt = 0; nt < 8; nt++) {
                int cl = wn * 64 + nt * 8 + (lane & 3) * 2;
                float bb0 = bias[n0 + cl], bb1 = bias[n0 + cl + 1];
                smh[cl * 136 + rl]           = __float2half_rn(acc[mt][nt][0] + bb0);
                smh[(cl + 1) * 136 + rl]     = __float2half_rn(acc[mt][nt][1] + bb1);
                smh[cl * 136 + rl + 8]       = __float2half_rn(acc[mt][nt][2] + bb0);
                smh[(cl + 1) * 136 + rl + 8] = __float2half_rn(acc[mt][nt][3] + bb1);
            }
        }
        __syncthreads();
        int bh = (m0 >> 11) * NHEADS + (n0 >> 7);
        int s0 = m0 & (SEQ - 1);
        __half* vbase = VT16 + (size_t)bh * DK * SEQ + s0;
#pragma unroll
        for (int i = 0; i < 16; i++) {
            int idx = tid + i * 128;
            int row = idx >> 4, seg = idx & 15;
            uint4 v = *(uint4*)&smh[row * 136 + seg * 8];
            *(uint4*)&vbase[(size_t)row * SEQ + seg * 8] = v;
        }
        return;
    }

    const float ropescale = (bz == 0) ? 0.08838834764831843f : 1.0f;
    __half* C16 = (bz == 0) ? Q16 : K16;
#pragma unroll
    for (int mt = 0; mt < 4; mt++) {
        int r = m0 + wm * 64 + mt * 16 + (lane >> 2);
        int s_pos0 = r & (SEQ - 1);
#pragma unroll
        for (int nt = 0; nt < 8; nt++) {
            int gc = n0 + wn * 64 + nt * 8 + (lane & 3) * 2;
            float bb0 = bias[gc], bb1 = bias[gc + 1];
            float e0 = acc[mt][nt][0] + bb0, o0 = acc[mt][nt][1] + bb1;
            float e1 = acc[mt][nt][2] + bb0, o1 = acc[mt][nt][3] + bb1;
            int i = (gc & (DK - 1)) >> 1;
            float inv_freq = powf(10000.0f, -((float)(2 * i)) / 128.0f);
            float c0r, s0r, c1r, s1r;
            sincosf((float)s_pos0 * inv_freq, &s0r, &c0r);
            sincosf((float)(s_pos0 + 8) * inv_freq, &s1r, &c1r);
            float re0 = (e0 * c0r - o0 * s0r) * ropescale;
            float ro0 = (e0 * s0r + o0 * c0r) * ropescale;
            float re1 = (e1 * c1r - o1 * s1r) * ropescale;
            float ro1 = (e1 * s1r + o1 * c1r) * ropescale;
            *(uint32_t*)&C16[(size_t)r * DMODEL + gc] = packh2(re0, ro0);
            *(uint32_t*)&C16[(size_t)(r + 8) * DMODEL + gc] = packh2(re1, ro1);
        }
    }
}

__global__ __launch_bounds__(128, 2)
void gemm_f16(const __half* __restrict__ A, const __half* __restrict__ B,
              const float* __restrict__ bias, float* __restrict__ C)
{
    extern __shared__ __half smh[];
    const int tid = threadIdx.x, lane = tid & 31, wid = tid >> 5;
    const int wm = wid & 1, wn = wid >> 1;
    const int m0 = blockIdx.y * 128, n0 = blockIdx.x * 128;
    const uint32_t sb = smem_u32(smh);

    auto issue = [&](int kt, int stg) {
        int kofs = kt * 64;
#pragma unroll
        for (int i = 0; i < 16; i++) {
            int idx = tid + i * 128;
            int plane = idx >> 10, rem = idx & 1023;
            int row = rem >> 3, ch = (rem & 7) * 8;
            const __half* src = plane ? (B + (size_t)(n0 + row) * DMODEL + kofs + ch)
                                      : (A + (size_t)(m0 + row) * DMODEL + kofs + ch);
            cpasync16(sb + (stg * STGE64 + plane * PLE64 + row * 72 + ch) * 2, src);
        }
    };

    float acc[4][8][4];
#pragma unroll
    for (int a = 0; a < 4; a++)
#pragma unroll
        for (int b = 0; b < 8; b++)
#pragma unroll
            for (int c = 0; c < 4; c++) acc[a][b][c] = 0.f;

    issue(0, 0); CP_COMMIT;

    for (int kt = 0; kt < NKIT; kt++) {
        cp_wait<0>();
        __syncthreads();
        if (kt + 1 < NKIT) { issue(kt + 1, (kt + 1) & 1); CP_COMMIT; }
        uint32_t s0 = sb + ((kt & 1) * STGE64) * 2;

#pragma unroll
        for (int ks = 0; ks < 64; ks += 16) {
            uint32_t av[4][4], bv[4][4];
#pragma unroll
            for (int mt = 0; mt < 4; mt++) {
                int ar = wm * 64 + mt * 16 + (lane & 15);
                int ac = ks + ((lane >> 4) << 3);
                uint32_t off = (uint32_t)(ar * 72 + ac) * 2;
                ldmx4(av[mt][0], av[mt][1], av[mt][2], av[mt][3], s0 + off);
            }
#pragma unroll
            for (int np = 0; np < 4; np++) {
                int br = wn * 64 + np * 16 + ((lane >> 4) << 3) + (lane & 7);
                int bc = ks + (((lane >> 3) & 1) << 3);
                uint32_t off = (uint32_t)(br * 72 + bc) * 2;
                ldmx4(bv[np][0], bv[np][1], bv[np][2], bv[np][3], s0 + PLE64 * 2 + off);
            }
#pragma unroll
            for (int np = 0; np < 4; np++)
#pragma unroll
                for (int mt = 0; mt < 4; mt++) {
                    mma_f16(acc[mt][2 * np],     av[mt][0], av[mt][1], av[mt][2], av[mt][3], bv[np][0], bv[np][1]);
                    mma_f16(acc[mt][2 * np + 1], av[mt][0], av[mt][1], av[mt][2], av[mt][3], bv[np][2], bv[np][3]);
                }
        }
        __syncthreads();
    }

#pragma unroll
    for (int mt = 0; mt < 4; mt++) {
        int r = m0 + wm * 64 + mt * 16 + (lane >> 2);
#pragma unroll
        for (int nt = 0; nt < 8; nt++) {
            int gc = n0 + wn * 64 + nt * 8 + (lane & 3) * 2;
            float bb0 = bias[gc], bb1 = bias[gc + 1];
            float2 v0 = {acc[mt][nt][0] + bb0, acc[mt][nt][1] + bb1};
            float2 v1 = {acc[mt][nt][2] + bb0, acc[mt][nt][3] + bb1};
            *(float2*)&C[(size_t)r * DMODEL + gc] = v0;
            *(float2*)&C[(size_t)(r + 8) * DMODEL + gc] = v1;
        }
    }
}

// ---------------- Flash attention, fp16, paired q-blocks (unchanged) ---------
#define FQ  0
#define FK  8704
#define FV  17408
#define FTOT 26624

__global__ __launch_bounds__(128, 3)
void flash_mma(const __half* __restrict__ Q16, const __half* __restrict__ K16,
               const __half* __restrict__ V16, __half* __restrict__ A16)
{
    extern __shared__ __half smf[];
    const uint32_t sb = smem_u32(smf);
    const int tid = threadIdx.x, lane = tid & 31, warp = tid >> 5;
    const int bx = blockIdx.x, bh = blockIdx.y;
    const int b = bh >> 4, h = bh & 15;
    const int hofs = h * DK;
    const __half* vtbase = V16 + (size_t)bh * DK * SEQ;

    for (int pass = 0; pass < 2; pass++) {
        const int qblk = pass ? (31 - bx) : bx;
        const int q0 = qblk * 64;
        const size_t qrow0 = (size_t)(b * SEQ + q0);

#pragma unroll
        for (int i = 0; i < 8; i++) {
            int idx = tid + i * 128;
            int r = idx >> 4, c = (idx & 15) * 8;
            cpasync16(sb + (FQ + r * 136 + c) * 2, Q16 + (qrow0 + r) * DMODEL + hofs + c);
        }
        CP_COMMIT;

        float o[16][4];
#pragma unroll
        for (int t = 0; t < 16; t++)
#pragma unroll
            for (int e = 0; e < 4; e++) o[t][e] = 0.f;
        float m0v = -INFINITY, m1v = -INFINITY, l0v = 0.f, l1v = 0.f;

        for (int jb = 0; jb <= qblk; ++jb) {
            const int k0 = jb * 64;
            const size_t krow0 = (size_t)(b * SEQ + k0);
#pragma unroll
            for (int i = 0; i < 8; i++) {
                int idx = tid + i * 128;
                int r = idx >> 4, c = (idx & 15) * 8;
                cpasync16(sb + (FK + r * 136 + c) * 2, K16 + (krow0 + r) * DMODEL + hofs + c);
            }
#pragma unroll
            for (int i = 0; i < 8; i++) {
                int idx = tid + i * 128;
                int d = idx >> 3, c = (idx & 7) * 8;
                cpasync16(sb + (FV + d * 72 + c) * 2, vtbase + (size_t)d * SEQ + k0 + c);
            }
            CP_COMMIT; cp_wait<0>();
            __syncthreads();

            float s[8][4];
#pragma unroll
            for (int t = 0; t < 8; t++)
#pragma unroll
                for (int e = 0; e < 4; e++) s[t][e] = 0.f;

#pragma unroll
            for (int kc = 0; kc < 8; kc++) {
                int ar = warp * 16 + (lane & 15);
                int ac = kc * 16 + ((lane >> 4) << 3);
                uint32_t aoff = (uint32_t)(ar * 136 + ac) * 2;
                uint32_t q0r, q1r, q2r, q3r;
                ldmx4(q0r, q1r, q2r, q3r, sb + FQ * 2 + aoff);
#pragma unroll
                for (int np = 0; np < 4; np++) {
                    int br = np * 16 + ((lane >> 4) << 3) + (lane & 7);
                    int bc = kc * 16 + (((lane >> 3) & 1) << 3);
                    uint32_t boff = (uint32_t)(br * 136 + bc) * 2;
                    uint32_t k0r, k1r, k2r, k3r;
                    ldmx4(k0r, k1r, k2r, k3r, sb + FK * 2 + boff);
                    mma_f16(s[2 * np],     q0r, q1r, q2r, q3r, k0r, k1r);
                    mma_f16(s[2 * np + 1], q0r, q1r, q2r, q3r, k2r, k3r);
                }
            }

            if (jb == qblk) {
                int r0 = q0 + warp * 16 + (lane >> 2);
#pragma unroll
                for (int t = 0; t < 8; t++) {
                    int c0 = k0 + t * 8 + 2 * (lane & 3);
                    if (c0 > r0)     s[t][0] = -INFINITY;
                    if (c0 + 1 > r0) s[t][1] = -INFINITY;
                    if (c0 > r0 + 8)     s[t][2] = -INFINITY;
                    if (c0 + 1 > r0 + 8) s[t][3] = -INFINITY;
                }
            }

            float mx0 = -INFINITY, mx1 = -INFINITY;
#pragma unroll
            for (int t = 0; t < 8; t++) {
                mx0 = fmaxf(mx0, fmaxf(s[t][0], s[t][1]));
                mx1 = fmaxf(mx1, fmaxf(s[t][2], s[t][3]));
            }
            mx0 = fmaxf(mx0, __shfl_xor_sync(0xffffffffu, mx0, 1));
            mx0 = fmaxf(mx0, __shfl_xor_sync(0xffffffffu, mx0, 2));
            mx1 = fmaxf(mx1, __shfl_xor_sync(0xffffffffu, mx1, 1));
            mx1 = fmaxf(mx1, __shfl_xor_sync(0xffffffffu, mx1, 2));
            float mn0 = fmaxf(m0v, mx0), mn1 = fmaxf(m1v, mx1);
            float sc0 = __expf(m0v - mn0), sc1 = __expf(m1v - mn1);
            float sum0 = 0.f, sum1 = 0.f;
#pragma unroll
            for (int t = 0; t < 8; t++) {
                s[t][0] = __expf(s[t][0] - mn0); sum0 += s[t][0];
                s[t][1] = __expf(s[t][1] - mn0); sum0 += s[t][1];
                s[t][2] = __expf(s[t][2] - mn1); sum1 += s[t][2];
                s[t][3] = __expf(s[t][3] - mn1); sum1 += s[t][3];
            }
            sum0 += __shfl_xor_sync(0xffffffffu, sum0, 1);
            sum0 += __shfl_xor_sync(0xffffffffu, sum0, 2);
            sum1 += __shfl_xor_sync(0xffffffffu, sum1, 1);
            sum1 += __shfl_xor_sync(0xffffffffu, sum1, 2);
            l0v = l0v * sc0 + sum0; m0v = mn0;
            l1v = l1v * sc1 + sum1; m1v = mn1;

#pragma unroll
            for (int t = 0; t < 16; t++) {
                o[t][0] *= sc0; o[t][1] *= sc0; o[t][2] *= sc1; o[t][3] *= sc1;
            }

#pragma unroll
            for (int kc = 0; kc < 4; kc++) {
                uint32_t p0 = packh2(s[2 * kc][0],     s[2 * kc][1]);
                uint32_t p1 = packh2(s[2 * kc][2],     s[2 * kc][3]);
                uint32_t p2 = packh2(s[2 * kc + 1][0], s[2 * kc + 1][1]);
                uint32_t p3 = packh2(s[2 * kc + 1][2], s[2 * kc + 1][3]);
#pragma unroll
                for (int np = 0; np < 8; np++) {
                    int br = np * 16 + ((lane >> 4) << 3) + (lane & 7);
                    int bc = kc * 16 + (((lane >> 3) & 1) << 3);
                    uint32_t boff = (uint32_t)(br * 72 + bc) * 2;
                    uint32_t v0, v1, v2, v3;
                    ldmx4(v0, v1, v2, v3, sb + FV * 2 + boff);
                    mma_f16(o[2 * np],     p0, p1, p2, p3, v0, v1);
                    mma_f16(o[2 * np + 1], p0, p1, p2, p3, v2, v3);
                }
            }
            __syncthreads();
        }

        float inv0 = 1.f / l0v, inv1 = 1.f / l1v;
        int r0 = b * SEQ + q0 + warp * 16 + (lane >> 2);
#pragma unroll
        for (int t = 0; t < 16; t++) {
            int gc = hofs + t * 8 + 2 * (lane & 3);
            *(uint32_t*)&A16[(size_t)r0 * DMODEL + gc] = packh2(o[t][0] * inv0, o[t][1] * inv0);
            *(uint32_t*)&A16[(size_t)(r0 + 8) * DMODEL + gc] = packh2(o[t][2] * inv1, o[t][3] * inv1);
        }
    }
}

// ---------------- launch ------------------------------------------------------
extern "C" void kernel_launch(void* const* d_in, const int* in_sizes, int n_in,
                              void* d_out, int out_size)
{
    const float* x    = (const float*)d_in[0];
    const float* w[4] = {(const float*)d_in[1], (const float*)d_in[3],
                         (const float*)d_in[5], (const float*)d_in[7]};
    const float* bi[4] = {(const float*)d_in[2], (const float*)d_in[4],
                          (const float*)d_in[6], (const float*)d_in[8]};
    float* out = (float*)d_out;

    __half *x16, *w16, *wo16, *q16, *k16, *vt16, *a16;
    cudaGetSymbolAddress((void**)&x16, g_x16);
    cudaGetSymbolAddress((void**)&w16, g_w16);
    cudaGetSymbolAddress((void**)&wo16, g_wo16);
    cudaGetSymbolAddress((void**)&q16, g_q16);
    cudaGetSymbolAddress((void**)&k16, g_k16);
    cudaGetSymbolAddress((void**)&vt16, g_vt16);
    cudaGetSymbolAddress((void**)&a16, g_a16);

    convert_all<<<dim3(WN / 1024, 6), 256>>>(w[0], w[1], w[2], w[3], x,
                                             w16, wo16, x16);

    cudaFuncSetAttribute(gemm_proj, cudaFuncAttributeMaxDynamicSharedMemorySize,
                         GSMEM2);
    cudaFuncSetAttribute(gemm_f16, cudaFuncAttributeMaxDynamicSharedMemorySize,
                         GSMEM2);
    gemm_proj<<<dim3(DMODEL / 128, ROWS / 128, 3), 128, GSMEM2>>>(
        x16, w16, bi[0], bi[1], bi[2], q16, k16, vt16);

    size_t fsmem = FTOT * sizeof(__half);
    cudaFuncSetAttribute(flash_mma, cudaFuncAttributeMaxDynamicSharedMemorySize,
                         (int)fsmem);
    flash_mma<<<dim3(SEQ / 128, BATCH * NHEADS), 128, fsmem>>>(q16, k16, vt16, a16);

    gemm_f16<<<dim3(DMODEL / 128, ROWS / 128), 128, GSMEM2>>>(a16, wo16, bi[3], out);
}

// round 17
// speedup vs baseline: 1.0205x; 1.0205x over previous
#include <cuda_runtime.h>
#include <cuda_fp16.h>
#include <math.h>
#include <stdint.h>

#define BATCH   2
#define SEQ     2048
#define DMODEL  2048
#define NHEADS  16
#define DK      128
#define ROWS    (BATCH * SEQ)
#define WN      (DMODEL * DMODEL)

// ---------------- scratch ----------------------------------------------------
__device__ __half g_x16[ROWS * DMODEL];
__device__ __half g_w16[3][WN];
__device__ __half g_wo16[WN];
__device__ __half g_q16[ROWS * DMODEL];
__device__ __half g_k16[ROWS * DMODEL];
__device__ __half g_vt16[ROWS * DMODEL];   // [bh][d][s]
__device__ __half g_a16[ROWS * DMODEL];

// ---------------- helpers ----------------------------------------------------
__device__ __forceinline__ uint32_t smem_u32(const void* p) {
    return (uint32_t)__cvta_generic_to_shared(p);
}
__device__ __forceinline__ void ldmx4(uint32_t& r0, uint32_t& r1, uint32_t& r2,
                                      uint32_t& r3, uint32_t a) {
    asm volatile("ldmatrix.sync.aligned.m8n8.x4.shared.b16 {%0,%1,%2,%3},[%4];"
                 : "=r"(r0), "=r"(r1), "=r"(r2), "=r"(r3) : "r"(a));
}
__device__ __forceinline__ void mma_f16(float* c, uint32_t a0, uint32_t a1,
                                        uint32_t a2, uint32_t a3,
                                        uint32_t b0, uint32_t b1) {
    asm volatile(
        "mma.sync.aligned.m16n8k16.row.col.f32.f16.f16.f32 "
        "{%0,%1,%2,%3},{%4,%5,%6,%7},{%8,%9},{%0,%1,%2,%3};"
        : "+f"(c[0]), "+f"(c[1]), "+f"(c[2]), "+f"(c[3])
        : "r"(a0), "r"(a1), "r"(a2), "r"(a3), "r"(b0), "r"(b1));
}
__device__ __forceinline__ void cpasync16(uint32_t dst, const void* src) {
    asm volatile("cp.async.cg.shared.global [%0],[%1],16;" :: "r"(dst), "l"(src));
}
#define CP_COMMIT asm volatile("cp.async.commit_group;")
template<int N> __device__ __forceinline__ void cp_wait() {
    asm volatile("cp.async.wait_group %0;" :: "n"(N));
}
__device__ __forceinline__ uint32_t packh2(float x, float y) {
    __half2 h = __floats2half2_rn(x, y);
    return *(uint32_t*)&h;
}

// ---------------- merged converts --------------------------------------------
__global__ __launch_bounds__(256)
void convert_all(const float* __restrict__ w0, const float* __restrict__ w1,
                 const float* __restrict__ w2, const float* __restrict__ w3,
                 const float* __restrict__ x,
                 __half* __restrict__ wqkv, __half* __restrict__ wo16,
                 __half* __restrict__ x16)
{
    int z = blockIdx.y;
    const float* src;
    __half* dst;
    if (z < 4) {
        src = (z == 0) ? w0 : (z == 1) ? w1 : (z == 2) ? w2 : w3;
        dst = (z < 3) ? (wqkv + (size_t)z * WN) : wo16;
    } else {
        src = x + (size_t)(z - 4) * WN;
        dst = x16 + (size_t)(z - 4) * WN;
    }
    int i = (blockIdx.x * blockDim.x + threadIdx.x) * 4;
    float4 v = *(const float4*)(src + i);
    *(uint32_t*)&dst[i]     = packh2(v.x, v.y);
    *(uint32_t*)&dst[i + 2] = packh2(v.z, v.w);
}

// ---------------- fp16 GEMM, 3-stage BK=64, single sync (R15 best) -----------
#define NKIT   (DMODEL / 64)     // 32
#define PLE64  (128 * 72)
#define STGE64 (2 * PLE64)
#define GSMEM3 (3 * STGE64 * 2)  // 110592 B

// z = 0: Q (RoPE + 1/sqrt(dk)) | 1: K (RoPE) | 2: V (transposed per-head out)
__global__ __launch_bounds__(256, 2)
void gemm_proj(const __half* __restrict__ A, const __half* __restrict__ W,
               const float* __restrict__ b0, const float* __restrict__ b1,
               const float* __restrict__ b2,
               __half* __restrict__ Q16, __half* __restrict__ K16,
               __half* __restrict__ VT16)
{
    extern __shared__ __half smh[];
    const int tid = threadIdx.x, lane = tid & 31, wid = tid >> 5;
    const int wm = wid & 3, wn = wid >> 2;
    const int m0 = blockIdx.y * 128, n0 = blockIdx.x * 128;
    const int bz = blockIdx.z;
    const uint32_t sb = smem_u32(smh);
    const __half* B = W + (size_t)bz * WN;
    const float* bias = (bz == 0) ? b0 : (bz == 1) ? b1 : b2;

    auto issue = [&](int kt) {
        int stg = kt % 3;
        int kofs = kt * 64;
#pragma unroll
        for (int i = 0; i < 8; i++) {
            int idx = tid + i * 256;
            int plane = idx >> 10, rem = idx & 1023;
            int row = rem >> 3, ch = (rem & 7) * 8;
            const __half* src = plane ? (B + (size_t)(n0 + row) * DMODEL + kofs + ch)
                                      : (A + (size_t)(m0 + row) * DMODEL + kofs + ch);
            cpasync16(sb + (stg * STGE64 + plane * PLE64 + row * 72 + ch) * 2, src);
        }
    };

    float acc[2][8][4];
#pragma unroll
    for (int a = 0; a < 2; a++)
#pragma unroll
        for (int b = 0; b < 8; b++)
#pragma unroll
            for (int c = 0; c < 4; c++) acc[a][b][c] = 0.f;

    issue(0); CP_COMMIT;
    issue(1); CP_COMMIT;

    for (int kt = 0; kt < NKIT; kt++) {
        if (kt + 1 < NKIT) cp_wait<1>(); else cp_wait<0>();
        __syncthreads();
        if (kt + 2 < NKIT) { issue(kt + 2); CP_COMMIT; }
        uint32_t s0 = sb + ((kt % 3) * STGE64) * 2;

#pragma unroll
        for (int ks = 0; ks < 64; ks += 16) {
            uint32_t av[2][4];
#pragma unroll
            for (int mt = 0; mt < 2; mt++) {
                int ar = wm * 32 + mt * 16 + (lane & 15);
                int ac = ks + ((lane >> 4) << 3);
                uint32_t off = (uint32_t)(ar * 72 + ac) * 2;
                ldmx4(av[mt][0], av[mt][1], av[mt][2], av[mt][3], s0 + off);
            }
#pragma unroll
            for (int np = 0; np < 4; np++) {
                int br = wn * 64 + np * 16 + ((lane >> 4) << 3) + (lane & 7);
                int bc = ks + (((lane >> 3) & 1) << 3);
                uint32_t off = (uint32_t)(br * 72 + bc) * 2;
                uint32_t bv0, bv1, bv2, bv3;
                ldmx4(bv0, bv1, bv2, bv3, s0 + PLE64 * 2 + off);
#pragma unroll
                for (int mt = 0; mt < 2; mt++) {
                    mma_f16(acc[mt][2 * np],     av[mt][0], av[mt][1], av[mt][2], av[mt][3], bv0, bv1);
                    mma_f16(acc[mt][2 * np + 1], av[mt][0], av[mt][1], av[mt][2], av[mt][3], bv2, bv3);
                }
            }
        }
    }

    if (bz == 2) {
        __syncthreads();
#pragma unroll
        for (int mt = 0; mt < 2; mt++) {
            int rl = wm * 32 + mt * 16 + (lane >> 2);
#pragma unroll
            for (int nt = 0; nt < 8; nt++) {
                int cl = wn * 64 + nt * 8 + (lane & 3) * 2;
                float bb0 = bias[n0 + cl], bb1 = bias[n0 + cl + 1];
                smh[cl * 136 + rl]           = __float2half_rn(acc[mt][nt][0] + bb0);
                smh[(cl + 1) * 136 + rl]     = __float2half_rn(acc[mt][nt][1] + bb1);
                smh[cl * 136 + rl + 8]       = __float2half_rn(acc[mt][nt][2] + bb0);
                smh[(cl + 1) * 136 + rl + 8] = __float2half_rn(acc[mt][nt][3] + bb1);
            }
        }
        __syncthreads();
        int bh = (m0 >> 11) * NHEADS + (n0 >> 7);
        int s0 = m0 & (SEQ - 1);
        __half* vbase = VT16 + (size_t)bh * DK * SEQ + s0;
#pragma unroll
        for (int i = 0; i < 8; i++) {
            int idx = tid + i * 256;
            int row = idx >> 4, seg = idx & 15;
            uint4 v = *(uint4*)&smh[row * 136 + seg * 8];
            *(uint4*)&vbase[(size_t)row * SEQ + seg * 8] = v;
        }
        return;
    }

    const float ropescale = (bz == 0) ? 0.08838834764831843f : 1.0f;
    __half* C16 = (bz == 0) ? Q16 : K16;
#pragma unroll
    for (int mt = 0; mt < 2; mt++) {
        int r = m0 + wm * 32 + mt * 16 + (lane >> 2);
        int s_pos0 = r & (SEQ - 1);
#pragma unroll
        for (int nt = 0; nt < 8; nt++) {
            int gc = n0 + wn * 64 + nt * 8 + (lane & 3) * 2;
            float bb0 = bias[gc], bb1 = bias[gc + 1];
            float e0 = acc[mt][nt][0] + bb0, o0 = acc[mt][nt][1] + bb1;
            float e1 = acc[mt][nt][2] + bb0, o1 = acc[mt][nt][3] + bb1;
            int i = (gc & (DK - 1)) >> 1;
            float inv_freq = powf(10000.0f, -((float)(2 * i)) / 128.0f);
            float c0r, s0r, c1r, s1r;
            sincosf((float)s_pos0 * inv_freq, &s0r, &c0r);
            sincosf((float)(s_pos0 + 8) * inv_freq, &s1r, &c1r);
            float re0 = (e0 * c0r - o0 * s0r) * ropescale;
            float ro0 = (e0 * s0r + o0 * c0r) * ropescale;
            float re1 = (e1 * c1r - o1 * s1r) * ropescale;
            float ro1 = (e1 * s1r + o1 * c1r) * ropescale;
            *(uint32_t*)&C16[(size_t)r * DMODEL + gc] = packh2(re0, ro0);
            *(uint32_t*)&C16[(size_t)(r + 8) * DMODEL + gc] = packh2(re1, ro1);
        }
    }
}

__global__ __launch_bounds__(256, 2)
void gemm_f16(const __half* __restrict__ A, const __half* __restrict__ B,
              const float* __restrict__ bias, float* __restrict__ C)
{
    extern __shared__ __half smh[];
    const int tid = threadIdx.x, lane = tid & 31, wid = tid >> 5;
    const int wm = wid & 3, wn = wid >> 2;
    const int m0 = blockIdx.y * 128, n0 = blockIdx.x * 128;
    const uint32_t sb = smem_u32(smh);

    auto issue = [&](int kt) {
        int stg = kt % 3;
        int kofs = kt * 64;
#pragma unroll
        for (int i = 0; i < 8; i++) {
            int idx = tid + i * 256;
            int plane = idx >> 10, rem = idx & 1023;
            int row = rem >> 3, ch = (rem & 7) * 8;
            const __half* src = plane ? (B + (size_t)(n0 + row) * DMODEL + kofs + ch)
                                      : (A + (size_t)(m0 + row) * DMODEL + kofs + ch);
            cpasync16(sb + (stg * STGE64 + plane * PLE64 + row * 72 + ch) * 2, src);
        }
    };

    float acc[2][8][4];
#pragma unroll
    for (int a = 0; a < 2; a++)
#pragma unroll
        for (int b = 0; b < 8; b++)
#pragma unroll
            for (int c = 0; c < 4; c++) acc[a][b][c] = 0.f;

    issue(0); CP_COMMIT;
    issue(1); CP_COMMIT;

    for (int kt = 0; kt < NKIT; kt++) {
        if (kt + 1 < NKIT) cp_wait<1>(); else cp_wait<0>();
        __syncthreads();
        if (kt + 2 < NKIT) { issue(kt + 2); CP_COMMIT; }
        uint32_t s0 = sb + ((kt % 3) * STGE64) * 2;

#pragma unroll
        for (int ks = 0; ks < 64; ks += 16) {
            uint32_t av[2][4];
#pragma unroll
            for (int mt = 0; mt < 2; mt++) {
                int ar = wm * 32 + mt * 16 + (lane & 15);
                int ac = ks + ((lane >> 4) << 3);
                uint32_t off = (uint32_t)(ar * 72 + ac) * 2;
                ldmx4(av[mt][0], av[mt][1], av[mt][2], av[mt][3], s0 + off);
            }
#pragma unroll
            for (int np = 0; np < 4; np++) {
                int br = wn * 64 + np * 16 + ((lane >> 4) << 3) + (lane & 7);
                int bc = ks + (((lane >> 3) & 1) << 3);
                uint32_t off = (uint32_t)(br * 72 + bc) * 2;
                uint32_t bv0, bv1, bv2, bv3;
                ldmx4(bv0, bv1, bv2, bv3, s0 + PLE64 * 2 + off);
#pragma unroll
                for (int mt = 0; mt < 2; mt++) {
                    mma_f16(acc[mt][2 * np],     av[mt][0], av[mt][1], av[mt][2], av[mt][3], bv0, bv1);
                    mma_f16(acc[mt][2 * np + 1], av[mt][0], av[mt][1], av[mt][2], av[mt][3], bv2, bv3);
                }
            }
        }
    }

#pragma unroll
    for (int mt = 0; mt < 2; mt++) {
        int r = m0 + wm * 32 + mt * 16 + (lane >> 2);
#pragma unroll
        for (int nt = 0; nt < 8; nt++) {
            int gc = n0 + wn * 64 + nt * 8 + (lane & 3) * 2;
            float bb0 = bias[gc], bb1 = bias[gc + 1];
            float2 v0 = {acc[mt][nt][0] + bb0, acc[mt][nt][1] + bb1};
            float2 v1 = {acc[mt][nt][2] + bb0, acc[mt][nt][3] + bb1};
            *(float2*)&C[(size_t)r * DMODEL + gc] = v0;
            *(float2*)&C[(size_t)(r + 8) * DMODEL + gc] = v1;
        }
    }
}

// ---------------- Flash attention: BM=128 (8 warps), paired q-blocks ---------
#define FQ  0
#define FK  17408
#define FV  26112
#define FTOT 35328

__global__ __launch_bounds__(256, 2)
void flash_mma(const __half* __restrict__ Q16, const __half* __restrict__ K16,
               const __half* __restrict__ V16, __half* __restrict__ A16)
{
    extern __shared__ __half smf[];
    const uint32_t sb = smem_u32(smf);
    const int tid = threadIdx.x, lane = tid & 31, warp = tid >> 5;
    const int bx = blockIdx.x, bh = blockIdx.y;
    const int b = bh >> 4, h = bh & 15;
    const int hofs = h * DK;
    const __half* vtbase = V16 + (size_t)bh * DK * SEQ;

    // Two q-blocks of 128 rows per CTA: bx and 15-bx -> uniform 34 kv-iters.
    for (int pass = 0; pass < 2; pass++) {
        const int qblk = pass ? (15 - bx) : bx;
        const int q0 = qblk * 128;
        const size_t qrow0 = (size_t)(b * SEQ + q0);

#pragma unroll
        for (int i = 0; i < 8; i++) {
            int idx = tid + i * 256;
            int r = idx >> 4, c = (idx & 15) * 8;
            cpasync16(sb + (FQ + r * 136 + c) * 2, Q16 + (qrow0 + r) * DMODEL + hofs + c);
        }
        CP_COMMIT;

        float o[16][4];
#pragma unroll
        for (int t = 0; t < 16; t++)
#pragma unroll
            for (int e = 0; e < 4; e++) o[t][e] = 0.f;
        float m0v = -INFINITY, m1v = -INFINITY, l0v = 0.f, l1v = 0.f;

        const int nblk = 2 * qblk + 2;
        for (int jb = 0; jb < nblk; ++jb) {
            const int k0 = jb * 64;
            const size_t krow0 = (size_t)(b * SEQ + k0);
#pragma unroll
            for (int i = 0; i < 4; i++) {
                int idx = tid + i * 256;
                int r = idx >> 4, c = (idx & 15) * 8;
                cpasync16(sb + (FK + r * 136 + c) * 2, K16 + (krow0 + r) * DMODEL + hofs + c);
            }
#pragma unroll
            for (int i = 0; i < 4; i++) {
                int idx = tid + i * 256;
                int d = idx >> 3, c = (idx & 7) * 8;
                cpasync16(sb + (FV + d * 72 + c) * 2, vtbase + (size_t)d * SEQ + k0 + c);
            }
            CP_COMMIT; cp_wait<0>();
            __syncthreads();

            float s[8][4];
#pragma unroll
            for (int t = 0; t < 8; t++)
#pragma unroll
                for (int e = 0; e < 4; e++) s[t][e] = 0.f;

#pragma unroll
            for (int kc = 0; kc < 8; kc++) {
                int ar = warp * 16 + (lane & 15);
                int ac = kc * 16 + ((lane >> 4) << 3);
                uint32_t aoff = (uint32_t)(ar * 136 + ac) * 2;
                uint32_t q0r, q1r, q2r, q3r;
                ldmx4(q0r, q1r, q2r, q3r, sb + FQ * 2 + aoff);
#pragma unroll
                for (int np = 0; np < 4; np++) {
                    int br = np * 16 + ((lane >> 4) << 3) + (lane & 7);
                    int bc = kc * 16 + (((lane >> 3) & 1) << 3);
                    uint32_t boff = (uint32_t)(br * 136 + bc) * 2;
                    uint32_t k0r, k1r, k2r, k3r;
                    ldmx4(k0r, k1r, k2r, k3r, sb + FK * 2 + boff);
                    mma_f16(s[2 * np],     q0r, q1r, q2r, q3r, k0r, k1r);
                    mma_f16(s[2 * np + 1], q0r, q1r, q2r, q3r, k2r, k3r);
                }
            }

            if (jb >= nblk - 2) {
                int r0 = q0 + warp * 16 + (lane >> 2);
#pragma unroll
                for (int t = 0; t < 8; t++) {
                    int c0 = k0 + t * 8 + 2 * (lane & 3);
                    if (c0 > r0)     s[t][0] = -INFINITY;
                    if (c0 + 1 > r0) s[t][1] = -INFINITY;
                    if (c0 > r0 + 8)     s[t][2] = -INFINITY;
                    if (c0 + 1 > r0 + 8) s[t][3] = -INFINITY;
                }
            }

            float mx0 = -INFINITY, mx1 = -INFINITY;
#pragma unroll
            for (int t = 0; t < 8; t++) {
                mx0 = fmaxf(mx0, fmaxf(s[t][0], s[t][1]));
                mx1 = fmaxf(mx1, fmaxf(s[t][2], s[t][3]));
            }
            mx0 = fmaxf(mx0, __shfl_xor_sync(0xffffffffu, mx0, 1));
            mx0 = fmaxf(mx0, __shfl_xor_sync(0xffffffffu, mx0, 2));
            mx1 = fmaxf(mx1, __shfl_xor_sync(0xffffffffu, mx1, 1));
            mx1 = fmaxf(mx1, __shfl_xor_sync(0xffffffffu, mx1, 2));
            float mn0 = fmaxf(m0v, mx0), mn1 = fmaxf(m1v, mx1);
            float sc0 = __expf(m0v - mn0), sc1 = __expf(m1v - mn1);
            float sum0 = 0.f, sum1 = 0.f;
#pragma unroll
            for (int t = 0; t < 8; t++) {
                s[t][0] = __expf(s[t][0] - mn0); sum0 += s[t][0];
                s[t][1] = __expf(s[t][1] - mn0); sum0 += s[t][1];
                s[t][2] = __expf(s[t][2] - mn1); sum1 += s[t][2];
                s[t][3] = __expf(s[t][3] - mn1); sum1 += s[t][3];
            }
            sum0 += __shfl_xor_sync(0xffffffffu, sum0, 1);
            sum0 += __shfl_xor_sync(0xffffffffu, sum0, 2);
            sum1 += __shfl_xor_sync(0xffffffffu, sum1, 1);
            sum1 += __shfl_xor_sync(0xffffffffu, sum1, 2);
            l0v = l0v * sc0 + sum0; m0v = mn0;
            l1v = l1v * sc1 + sum1; m1v = mn1;

#pragma unroll
            for (int t = 0; t < 16; t++) {
                o[t][0] *= sc0; o[t][1] *= sc0; o[t][2] *= sc1; o[t][3] *= sc1;
            }

#pragma unroll
            for (int kc = 0; kc < 4; kc++) {
                uint32_t p0 = packh2(s[2 * kc][0],     s[2 * kc][1]);
                uint32_t p1 = packh2(s[2 * kc][2],     s[2 * kc][3]);
                uint32_t p2 = packh2(s[2 * kc + 1][0], s[2 * kc + 1][1]);
                uint32_t p3 = packh2(s[2 * kc + 1][2], s[2 * kc + 1][3]);
#pragma unroll
                for (int np = 0; np < 8; np++) {
                    int br = np * 16 + ((lane >> 4) << 3) + (lane & 7);
                    int bc = kc * 16 + (((lane >> 3) & 1) << 3);
                    uint32_t boff = (uint32_t)(br * 72 + bc) * 2;
                    uint32_t v0, v1, v2, v3;
                    ldmx4(v0, v1, v2, v3, sb + FV * 2 + boff);
                    mma_f16(o[2 * np],     p0, p1, p2, p3, v0, v1);
                    mma_f16(o[2 * np + 1], p0, p1, p2, p3, v2, v3);
                }
            }
            __syncthreads();
        }

        float inv0 = 1.f / l0v, inv1 = 1.f / l1v;
        int r0 = b * SEQ + q0 + warp * 16 + (lane >> 2);
#pragma unroll
        for (int t = 0; t < 16; t++) {
            int gc = hofs + t * 8 + 2 * (lane & 3);
            *(uint32_t*)&A16[(size_t)r0 * DMODEL + gc] = packh2(o[t][0] * inv0, o[t][1] * inv0);
            *(uint32_t*)&A16[(size_t)(r0 + 8) * DMODEL + gc] = packh2(o[t][2] * inv1, o[t][3] * inv1);
        }
    }
}

// ---------------- launch ------------------------------------------------------
extern "C" void kernel_launch(void* const* d_in, const int* in_sizes, int n_in,
                              void* d_out, int out_size)
{
    const float* x    = (const float*)d_in[0];
    const float* w[4] = {(const float*)d_in[1], (const float*)d_in[3],
                         (const float*)d_in[5], (const float*)d_in[7]};
    const float* bi[4] = {(const float*)d_in[2], (const float*)d_in[4],
                          (const float*)d_in[6], (const float*)d_in[8]};
    float* out = (float*)d_out;

    __half *x16, *w16, *wo16, *q16, *k16, *vt16, *a16;
    cudaGetSymbolAddress((void**)&x16, g_x16);
    cudaGetSymbolAddress((void**)&w16, g_w16);
    cudaGetSymbolAddress((void**)&wo16, g_wo16);
    cudaGetSymbolAddress((void**)&q16, g_q16);
    cudaGetSymbolAddress((void**)&k16, g_k16);
    cudaGetSymbolAddress((void**)&vt16, g_vt16);
    cudaGetSymbolAddress((void**)&a16, g_a16);

    convert_all<<<dim3(WN / 1024, 6), 256>>>(w[0], w[1], w[2], w[3], x,
                                             w16, wo16, x16);

    cudaFuncSetAttribute(gemm_proj, cudaFuncAttributeMaxDynamicSharedMemorySize,
                         GSMEM3);
    cudaFuncSetAttribute(gemm_f16, cudaFuncAttributeMaxDynamicSharedMemorySize,
                         GSMEM3);
    gemm_proj<<<dim3(DMODEL / 128, ROWS / 128, 3), 256, GSMEM3>>>(
        x16, w16, bi[0], bi[1], bi[2], q16, k16, vt16);

    size_t fsmem = FTOT * sizeof(__half);
    cudaFuncSetAttribute(flash_mma, cudaFuncAttributeMaxDynamicSharedMemorySize,
                         (int)fsmem);
    flash_mma<<<dim3(SEQ / 256, BATCH * NHEADS), 256, fsmem>>>(q16, k16, vt16, a16);

    gemm_f16<<<dim3(DMODEL / 128, ROWS / 128), 256, GSMEM3>>>(a16, wo16, bi[3], out);
}